// round 7
// baseline (speedup 1.0000x reference)
#include <cuda_runtime.h>
#include <cuda_bf16.h>
#include <cstdint>

#define N_USERS 10000
#define N_ITEMS 40000
#define N_TOT   50000
#define HID     64
#define NCOL    128
#define NNZ_    2000000
#define BATCH   8192
#define HOPS    3

// GEMM padding
#define MPAD    10112          // 79 * 128
#define KPAD    10112          // 316 * 32
#define KSPLIT  5056           // KPAD / 2
#define KCH2    158            // KSPLIT / 32
#define NITER   474            // 3 phases * KCH2

// smem stage: A 128 rows x 80B + B 128 rows x 80B  (BK=32 bf16 + 16B pad)
#define ROWB    80
#define ASZ     (128 * ROWB)
#define STAGE   (2 * ASZ)

// fused grid split
#define NGEMM   158            // 79 m-tiles * splitK 2
#define NSPB    138            // spmm blocks (296 total = one wave @ 2 CTA/SM)
#define NSPW    (NSPB * 8)     // spmm warps

// ---------------- scratch (__device__ globals; zero-init => padding stays 0) --
__device__ __nv_bfloat16 g_Ahi[(size_t)MPAD * KPAD];
__device__ __nv_bfloat16 g_Alo[(size_t)MPAD * KPAD];
__device__ __nv_bfloat16 g_Bhi[(size_t)128 * KPAD];
__device__ __nv_bfloat16 g_Blo[(size_t)128 * KPAD];
__device__ float g_C1[(size_t)MPAD * NCOL];
__device__ float g_C2[(size_t)MPAD * NCOL];
__device__ float g_Hs [N_USERS * NCOL];
__device__ float g_accS[N_USERS * NCOL];
__device__ float g_Ha [N_TOT * NCOL];
__device__ float g_Ha2[N_TOT * NCOL];
__device__ float g_accA[N_TOT * NCOL];

// ---------------- PTX helpers ------------------------------------------------
__device__ __forceinline__ void red_add_v4(float* addr, float x, float y, float z, float w) {
    asm volatile("red.global.add.v4.f32 [%0], {%1, %2, %3, %4};"
                 :: "l"(addr), "f"(x), "f"(y), "f"(z), "f"(w) : "memory");
}
__device__ __forceinline__ void red_add_v2(float* addr, float x, float y) {
    asm volatile("red.global.add.v2.f32 [%0], {%1, %2};"
                 :: "l"(addr), "f"(x), "f"(y) : "memory");
}

__device__ __forceinline__ uint32_t smem_u32(const void* p) {
    uint32_t a;
    asm("{ .reg .u64 t; cvta.to.shared.u64 t, %1; cvt.u32.u64 %0, t; }" : "=r"(a) : "l"(p));
    return a;
}

#define CPASYNC(dst, src) \
    asm volatile("cp.async.cg.shared.global [%0], [%1], 16;" :: "r"(dst), "l"(src) : "memory")
#define CPCOMMIT() asm volatile("cp.async.commit_group;" ::: "memory")
#define CPWAIT(n)  asm volatile("cp.async.wait_group %0;" :: "n"(n) : "memory")

#define LDSM4(r0, r1, r2, r3, addr)                                              \
    asm volatile("ldmatrix.sync.aligned.m8n8.x4.shared.b16 {%0,%1,%2,%3}, [%4];" \
                 : "=r"(r0), "=r"(r1), "=r"(r2), "=r"(r3) : "r"(addr))

#define MMA_BF16(d, a, b)                                                        \
    asm volatile("mma.sync.aligned.m16n8k16.row.col.f32.bf16.bf16.f32 "          \
                 "{%0,%1,%2,%3}, {%4,%5,%6,%7}, {%8,%9}, {%0,%1,%2,%3};"         \
                 : "+f"((d)[0]), "+f"((d)[1]), "+f"((d)[2]), "+f"((d)[3])        \
                 : "r"((a)[0]), "r"((a)[1]), "r"((a)[2]), "r"((a)[3]),           \
                   "r"((b)[0]), "r"((b)[1]))

// ---------------- split conversions ------------------------------------------
__global__ void conv_S(const float4* __restrict__ S4,
                       __nv_bfloat16* __restrict__ Ahi, __nv_bfloat16* __restrict__ Alo)
{
    int i = blockIdx.x * blockDim.x + threadIdx.x;
    if (i >= N_USERS * 2500) return;
    int m = i / 2500, k4 = i - m * 2500;
    float4 v = S4[i];
    size_t o = (size_t)m * KPAD + (size_t)k4 * 4;
    __nv_bfloat16 h0 = __float2bfloat16(v.x), h1 = __float2bfloat16(v.y);
    __nv_bfloat16 h2 = __float2bfloat16(v.z), h3 = __float2bfloat16(v.w);
    __nv_bfloat16 l0 = __float2bfloat16(v.x - __bfloat162float(h0));
    __nv_bfloat16 l1 = __float2bfloat16(v.y - __bfloat162float(h1));
    __nv_bfloat16 l2 = __float2bfloat16(v.z - __bfloat162float(h2));
    __nv_bfloat16 l3 = __float2bfloat16(v.w - __bfloat162float(h3));
    uint32_t* ph = reinterpret_cast<uint32_t*>(Ahi + o);
    uint32_t* pl = reinterpret_cast<uint32_t*>(Alo + o);
    ph[0] = (uint32_t)__bfloat16_as_ushort(h0) | ((uint32_t)__bfloat16_as_ushort(h1) << 16);
    ph[1] = (uint32_t)__bfloat16_as_ushort(h2) | ((uint32_t)__bfloat16_as_ushort(h3) << 16);
    pl[0] = (uint32_t)__bfloat16_as_ushort(l0) | ((uint32_t)__bfloat16_as_ushort(l1) << 16);
    pl[1] = (uint32_t)__bfloat16_as_ushort(l2) | ((uint32_t)__bfloat16_as_ushort(l3) << 16);
}

// h [N_USERS x 128] f32  ->  Bt_hi/Bt_lo [128 x KPAD] bf16 (transposed split)
__global__ void conv_Bt(const float* __restrict__ h,
                        __nv_bfloat16* __restrict__ Bhi, __nv_bfloat16* __restrict__ Blo)
{
    __shared__ float t[32][33];
    int k0 = blockIdx.x * 32;
    int n0 = blockIdx.y * 32;
    int tx = threadIdx.x, ty = threadIdx.y;   // 32 x 8
#pragma unroll
    for (int r = 0; r < 4; r++) {
        int k = k0 + ty + r * 8;
        if (k < N_USERS) t[ty + r * 8][tx] = h[(size_t)k * NCOL + n0 + tx];
    }
    __syncthreads();
#pragma unroll
    for (int r = 0; r < 4; r++) {
        int n = n0 + ty + r * 8;
        int k = k0 + tx;
        if (k < N_USERS) {
            float v = t[tx][ty + r * 8];
            __nv_bfloat16 hi = __float2bfloat16(v);
            __nv_bfloat16 lo = __float2bfloat16(v - __bfloat162float(hi));
            Bhi[(size_t)n * KPAD + k] = hi;
            Blo[(size_t)n * KPAD + k] = lo;
        }
    }
}

// ---------------- fused hop: blocks [0,NGEMM) gemm | [NGEMM,+NSPB) spmm ------
// GEMM body identical to the R4-passing kernel (BK=32, double-buffered cp.async).
__global__ __launch_bounds__(256)
void fused_hop(const __nv_bfloat16* __restrict__ Ahi, const __nv_bfloat16* __restrict__ Alo,
               const __nv_bfloat16* __restrict__ Bhi, const __nv_bfloat16* __restrict__ Blo,
               float* __restrict__ C,
               const int* __restrict__ rows, const int* __restrict__ cols,
               const float* __restrict__ vals,
               const float* __restrict__ H, float* __restrict__ Hout)
{
    __shared__ __align__(16) char smem[2 * STAGE];

    const int tid = threadIdx.x;
    const int lane = tid & 31;

    if (blockIdx.x >= NGEMM) {
        // ---------------- SpMM path: grid-strided warps over 2M edges --------
        int warp = (blockIdx.x - NGEMM) * 8 + (tid >> 5);
#pragma unroll 1
        for (int e = warp; e < NNZ_; e += NSPW) {
            int r = rows[e];
            int c = cols[e];
            float v = vals[e];
            const float4 h = *(const float4*)(H + (size_t)c * NCOL + lane * 4);
            red_add_v4(Hout + (size_t)r * NCOL + lane * 4,
                       h.x * v, h.y * v, h.z * v, h.w * v);
        }
        return;
    }

    // ---------------- GEMM path (R4-proven body) -----------------------------
    const uint32_t sbase = smem_u32(smem);
    const int wid = tid >> 5;
    const int wm = (wid >> 2) * 64;        // warp M offset in tile
    const int wn = (wid & 3) * 32;         // warp N offset
    const int m0 = (blockIdx.x >> 1) * 128;
    const size_t kbase = (size_t)(blockIdx.x & 1) * KSPLIT;

    float d[4][4][4];
#pragma unroll
    for (int a = 0; a < 4; a++)
#pragma unroll
        for (int b = 0; b < 4; b++)
#pragma unroll
            for (int c = 0; c < 4; c++) d[a][b][c] = 0.f;

    const int lr  = tid >> 2;          // 0..63 base row (x2)
    const int lc  = tid & 3;           // 16B chunk within 64B row segment

    const int arow = (lane & 7) + ((lane >> 3) & 1) * 8;
    const int acol = (lane >> 4) * 16;
    const int brow = ((lane >> 4) * 8) + (lane & 7);
    const int bcol = ((lane >> 3) & 1) * 16;

#define PREFETCH(IT)                                                              \
    {                                                                             \
        int ph = (IT) / KCH2;                                                     \
        int kc = (IT) - ph * KCH2;                                                \
        const __nv_bfloat16* Ap = (ph == 2) ? Alo : Ahi;                          \
        const __nv_bfloat16* Bp = (ph == 1) ? Blo : Bhi;                          \
        size_t koff = kbase + (size_t)kc * 32;                                    \
        uint32_t dA = sbase + ((IT) & 1) * STAGE;                                 \
        uint32_t dB = dA + ASZ;                                                   \
        _Pragma("unroll")                                                         \
        for (int j = 0; j < 2; j++) {                                             \
            int r = lr + j * 64;                                                  \
            CPASYNC(dA + r * ROWB + lc * 16,                                      \
                    Ap + (size_t)(m0 + r) * KPAD + koff + lc * 8);                \
            CPASYNC(dB + r * ROWB + lc * 16,                                      \
                    Bp + (size_t)r * KPAD + koff + lc * 8);                       \
        }                                                                         \
    }

    PREFETCH(0)
    CPCOMMIT();

#pragma unroll 1
    for (int it = 0; it < NITER; it++) {
        if (it + 1 < NITER) {
            PREFETCH(it + 1)
            CPCOMMIT();
            CPWAIT(1);
        } else {
            CPWAIT(0);
        }
        __syncthreads();

        uint32_t sA = sbase + (it & 1) * STAGE;
        uint32_t sB = sA + ASZ;

#pragma unroll
        for (int kk = 0; kk < 2; kk++) {           // two k16 steps in BK=32
            uint32_t a[4][4], b[4][2];
#pragma unroll
            for (int mt = 0; mt < 4; mt++) {
                uint32_t addr = sA + (wm + mt * 16 + arow) * ROWB + kk * 32 + acol;
                LDSM4(a[mt][0], a[mt][1], a[mt][2], a[mt][3], addr);
            }
#pragma unroll
            for (int bt = 0; bt < 2; bt++) {
                uint32_t addr = sB + (wn + bt * 16 + brow) * ROWB + kk * 32 + bcol;
                LDSM4(b[bt * 2][0], b[bt * 2][1], b[bt * 2 + 1][0], b[bt * 2 + 1][1], addr);
            }
#pragma unroll
            for (int mt = 0; mt < 4; mt++)
#pragma unroll
                for (int nt = 0; nt < 4; nt++)
                    MMA_BF16(d[mt][nt], a[mt], b[nt]);
        }
        __syncthreads();
    }

    // epilogue: red.global.add.v2 into zeroed C (split-K accumulate)
    const int rbase = m0 + wm + (lane >> 2);
    const int cbase = wn + 2 * (lane & 3);
#pragma unroll
    for (int mt = 0; mt < 4; mt++) {
        int r0 = rbase + mt * 16;
#pragma unroll
        for (int nt = 0; nt < 4; nt++) {
            int c = cbase + nt * 8;
            red_add_v2(C + (size_t)r0 * NCOL + c,       d[mt][nt][0], d[mt][nt][1]);
            red_add_v2(C + (size_t)(r0 + 8) * NCOL + c, d[mt][nt][2], d[mt][nt][3]);
        }
    }
}

// ---------------- init kernels ----------------------------------------------
__global__ void init_social(const float* __restrict__ ue, const float* __restrict__ u1,
                            float* __restrict__ H, float* __restrict__ acc) {
    int idx = blockIdx.x * blockDim.x + threadIdx.x;
    if (idx >= N_USERS * HID) return;
    int u = idx >> 6, c = idx & 63;
    float a = ue[idx], b = u1[idx];
    H[u * NCOL + c] = a;        H[u * NCOL + 64 + c] = b;
    acc[u * NCOL + c] = a;      acc[u * NCOL + 64 + c] = b;
}

__global__ void init_ui(const float* __restrict__ ue, const float* __restrict__ ie,
                        const float* __restrict__ u2, const float* __restrict__ i2,
                        float* __restrict__ H, float* __restrict__ acc) {
    int idx = blockIdx.x * blockDim.x + threadIdx.x;
    if (idx >= N_TOT * HID) return;
    int n = idx >> 6, c = idx & 63;
    float a, b;
    if (n < N_USERS) { a = ue[n * 64 + c];              b = u2[n * 64 + c]; }
    else             { int m = n - N_USERS; a = ie[(size_t)m * 64 + c]; b = i2[(size_t)m * 64 + c]; }
    H[n * NCOL + c] = a;        H[n * NCOL + 64 + c] = b;
    acc[n * NCOL + c] = a;      acc[n * NCOL + 64 + c] = b;
}

// ---------------- fused accumulate: aS += cS  and  aA += cA ------------------
__global__ void add_both(float4* __restrict__ aS, const float4* __restrict__ cS,
                         float4* __restrict__ aA, const float4* __restrict__ cA)
{
    const int nS = N_USERS * NCOL / 4;
    const int nA = N_TOT * NCOL / 4;
    int i = blockIdx.x * blockDim.x + threadIdx.x;
    if (i < nS) {
        float4 a = aS[i], b = cS[i];
        a.x += b.x; a.y += b.y; a.z += b.z; a.w += b.w;
        aS[i] = a;
    } else if (i < nS + nA) {
        int j = i - nS;
        float4 a = aA[j], b = cA[j];
        a.x += b.x; a.y += b.y; a.z += b.z; a.w += b.w;
        aA[j] = a;
    }
}

// ---------------- finalize ---------------------------------------------------
__global__ void finalize(const float* __restrict__ accS, const float* __restrict__ accA,
                         const float* __restrict__ item1,
                         const int* __restrict__ users, const int* __restrict__ pos,
                         const int* __restrict__ neg, float* __restrict__ out)
{
    const int TOTROWS = 9 * BATCH + 2 * N_USERS;
    int gid = blockIdx.x * blockDim.x + threadIdx.x;
    if (gid >= TOTROWS * 64) return;
    int row = gid >> 6, c = gid & 63;
    float v;
    if (row < BATCH) {
        int u = users[row];
        v = (accS[u * NCOL + c] + accA[u * NCOL + c]) * 0.125f;
    } else if (row < 2 * BATCH) {
        int i = pos[row - BATCH];
        v = accA[(size_t)(N_USERS + i) * NCOL + c] * 0.25f;
    } else if (row < 3 * BATCH) {
        int i = neg[row - 2 * BATCH];
        v = accA[(size_t)(N_USERS + i) * NCOL + c] * 0.25f;
    } else if (row < 3 * BATCH + N_USERS) {
        int u = row - 3 * BATCH;
        v = accS[u * NCOL + c] * 0.25f;
    } else if (row < 3 * BATCH + 2 * N_USERS) {
        int u = row - 3 * BATCH - N_USERS;
        v = accA[u * NCOL + c] * 0.25f;
    } else if (row < 4 * BATCH + 2 * N_USERS) {
        int u = users[row - 3 * BATCH - 2 * N_USERS];
        v = accS[u * NCOL + 64 + c] * 0.25f;
    } else if (row < 5 * BATCH + 2 * N_USERS) {
        int i = pos[row - 4 * BATCH - 2 * N_USERS];
        v = item1[(size_t)i * 64 + c];
    } else if (row < 6 * BATCH + 2 * N_USERS) {
        int i = neg[row - 5 * BATCH - 2 * N_USERS];
        v = item1[(size_t)i * 64 + c];
    } else if (row < 7 * BATCH + 2 * N_USERS) {
        int u = users[row - 6 * BATCH - 2 * N_USERS];
        v = accA[u * NCOL + 64 + c] * 0.25f;
    } else if (row < 8 * BATCH + 2 * N_USERS) {
        int i = pos[row - 7 * BATCH - 2 * N_USERS];
        v = accA[(size_t)(N_USERS + i) * NCOL + 64 + c] * 0.25f;
    } else {
        int i = neg[row - 8 * BATCH - 2 * N_USERS];
        v = accA[(size_t)(N_USERS + i) * NCOL + 64 + c] * 0.25f;
    }
    out[gid] = v;
}

// ---------------- launch (single stream — no stream/event APIs) --------------
extern "C" void kernel_launch(void* const* d_in, const int* in_sizes, int n_in,
                              void* d_out, int out_size)
{
    const int*   users = (const int*)d_in[0];
    const int*   pos   = (const int*)d_in[1];
    const int*   neg   = (const int*)d_in[2];
    const float* ue    = (const float*)d_in[3];
    const float* ie    = (const float*)d_in[4];
    const float* u1    = (const float*)d_in[5];
    const float* i1    = (const float*)d_in[6];
    const float* u2    = (const float*)d_in[7];
    const float* i2    = (const float*)d_in[8];
    const float* S     = (const float*)d_in[9];
    const int*   arows = (const int*)d_in[10];
    const int*   acols = (const int*)d_in[11];
    const float* avals = (const float*)d_in[12];
    float* out = (float*)d_out;

    __nv_bfloat16 *Ahi, *Alo, *Bhi, *Blo;
    float *C1, *C2, *Hs, *aS, *Ha, *Ha2, *aA;
    cudaGetSymbolAddress((void**)&Ahi, g_Ahi);
    cudaGetSymbolAddress((void**)&Alo, g_Alo);
    cudaGetSymbolAddress((void**)&Bhi, g_Bhi);
    cudaGetSymbolAddress((void**)&Blo, g_Blo);
    cudaGetSymbolAddress((void**)&C1,  g_C1);
    cudaGetSymbolAddress((void**)&C2,  g_C2);
    cudaGetSymbolAddress((void**)&Hs,  g_Hs);
    cudaGetSymbolAddress((void**)&aS,  g_accS);
    cudaGetSymbolAddress((void**)&Ha,  g_Ha);
    cudaGetSymbolAddress((void**)&Ha2, g_Ha2);
    cudaGetSymbolAddress((void**)&aA,  g_accA);

    init_social<<<(N_USERS * HID + 255) / 256, 256>>>(ue, u1, Hs, aS);
    init_ui<<<(N_TOT * HID + 255) / 256, 256>>>(ue, ie, u2, i2, Ha, aA);
    conv_S<<<(N_USERS * 2500 + 255) / 256, 256>>>((const float4*)S, Ahi, Alo);

    // 3 fused hops: dense GEMM tile blocks + sparse SpMM blocks in one launch
    {
        float* dCur = Hs;
        float* sCur = Ha; float* sNxt = Ha2;
        for (int h = 0; h < HOPS; h++) {
            conv_Bt<<<dim3((N_USERS + 31) / 32, 4), dim3(32, 8)>>>(dCur, Bhi, Blo);
            float* dNxt = (h & 1) ? C2 : C1;
            cudaMemsetAsync(dNxt, 0, (size_t)MPAD * NCOL * sizeof(float));
            cudaMemsetAsync(sNxt, 0, (size_t)N_TOT * NCOL * sizeof(float));
            fused_hop<<<NGEMM + NSPB, 256>>>(Ahi, Alo, Bhi, Blo, dNxt,
                                             arows, acols, avals, sCur, sNxt);
            {
                const int ntot = N_USERS * NCOL / 4 + N_TOT * NCOL / 4;
                add_both<<<(ntot + 255) / 256, 256>>>(
                    (float4*)aS, (const float4*)dNxt, (float4*)aA, (const float4*)sNxt);
            }
            dCur = dNxt;
            float* t = sCur; sCur = sNxt; sNxt = t;
        }
    }

    const int totrows = 9 * BATCH + 2 * N_USERS;
    finalize<<<(totrows * 64 + 255) / 256, 256>>>(aS, aA, i1, users, pos, neg, out);
}

// round 9
// speedup vs baseline: 1.8006x; 1.8006x over previous
#include <cuda_runtime.h>
#include <cuda_bf16.h>
#include <cstdint>

#define N_USERS 10000
#define N_ITEMS 40000
#define N_TOT   50000
#define HID     64
#define NCOL    128
#define NNZ_    2000000
#define BATCH   8192
#define HOPS    3

// GEMM padding
#define MPAD    10112          // 79 * 128
#define KPAD    10112          // 316 * 32
#define KSPLITN 4
#define KSPLIT  2528           // KPAD / 4
#define KCH2    79             // KSPLIT / 32
#define NITER   237            // 3 phases * KCH2

// smem stage: A 128 rows x 80B + B 128 rows x 80B
#define ROWB    80
#define ASZ     (128 * ROWB)
#define STAGE   (2 * ASZ)

// ---------------- scratch (__device__ globals; zero-init => padding stays 0) --
__device__ __nv_bfloat16 g_Ahi[(size_t)MPAD * KPAD];
__device__ __nv_bfloat16 g_Alo[(size_t)MPAD * KPAD];
__device__ __nv_bfloat16 g_Bhi[(size_t)128 * KPAD];
__device__ __nv_bfloat16 g_Blo[(size_t)128 * KPAD];
__device__ float g_C1[(size_t)MPAD * NCOL];
__device__ float g_C2[(size_t)MPAD * NCOL];
__device__ float g_Hs [N_USERS * NCOL];
__device__ float g_accS[N_USERS * NCOL];
__device__ float g_Ha [N_TOT * NCOL];
__device__ float g_Ha2[N_TOT * NCOL];
__device__ float g_accA[N_TOT * NCOL];

// ---------------- PTX helpers ------------------------------------------------
__device__ __forceinline__ void red_add_v4(float* addr, float x, float y, float z, float w) {
    asm volatile("red.global.add.v4.f32 [%0], {%1, %2, %3, %4};"
                 :: "l"(addr), "f"(x), "f"(y), "f"(z), "f"(w) : "memory");
}
__device__ __forceinline__ void red_add_v2(float* addr, float x, float y) {
    asm volatile("red.global.add.v2.f32 [%0], {%1, %2};"
                 :: "l"(addr), "f"(x), "f"(y) : "memory");
}

__device__ __forceinline__ uint32_t smem_u32(const void* p) {
    uint32_t a;
    asm("{ .reg .u64 t; cvta.to.shared.u64 t, %1; cvt.u32.u64 %0, t; }" : "=r"(a) : "l"(p));
    return a;
}

#define CPASYNC(dst, src) \
    asm volatile("cp.async.cg.shared.global [%0], [%1], 16;" :: "r"(dst), "l"(src) : "memory")
#define CPCOMMIT() asm volatile("cp.async.commit_group;" ::: "memory")
#define CPWAIT(n)  asm volatile("cp.async.wait_group %0;" :: "n"(n) : "memory")

#define LDSM4(r0, r1, r2, r3, addr)                                              \
    asm volatile("ldmatrix.sync.aligned.m8n8.x4.shared.b16 {%0,%1,%2,%3}, [%4];" \
                 : "=r"(r0), "=r"(r1), "=r"(r2), "=r"(r3) : "r"(addr))

#define MMA_BF16(d, a, b)                                                        \
    asm volatile("mma.sync.aligned.m16n8k16.row.col.f32.bf16.bf16.f32 "          \
                 "{%0,%1,%2,%3}, {%4,%5,%6,%7}, {%8,%9}, {%0,%1,%2,%3};"         \
                 : "+f"((d)[0]), "+f"((d)[1]), "+f"((d)[2]), "+f"((d)[3])        \
                 : "r"((a)[0]), "r"((a)[1]), "r"((a)[2]), "r"((a)[3]),           \
                   "r"((b)[0]), "r"((b)[1]))

// ---------------- split conversions ------------------------------------------
__global__ void conv_S(const float4* __restrict__ S4,
                       __nv_bfloat16* __restrict__ Ahi, __nv_bfloat16* __restrict__ Alo)
{
    int i = blockIdx.x * blockDim.x + threadIdx.x;
    if (i >= N_USERS * 2500) return;
    int m = i / 2500, k4 = i - m * 2500;
    float4 v = S4[i];
    size_t o = (size_t)m * KPAD + (size_t)k4 * 4;
    __nv_bfloat16 h0 = __float2bfloat16(v.x), h1 = __float2bfloat16(v.y);
    __nv_bfloat16 h2 = __float2bfloat16(v.z), h3 = __float2bfloat16(v.w);
    __nv_bfloat16 l0 = __float2bfloat16(v.x - __bfloat162float(h0));
    __nv_bfloat16 l1 = __float2bfloat16(v.y - __bfloat162float(h1));
    __nv_bfloat16 l2 = __float2bfloat16(v.z - __bfloat162float(h2));
    __nv_bfloat16 l3 = __float2bfloat16(v.w - __bfloat162float(h3));
    uint32_t* ph = reinterpret_cast<uint32_t*>(Ahi + o);
    uint32_t* pl = reinterpret_cast<uint32_t*>(Alo + o);
    ph[0] = (uint32_t)__bfloat16_as_ushort(h0) | ((uint32_t)__bfloat16_as_ushort(h1) << 16);
    ph[1] = (uint32_t)__bfloat16_as_ushort(h2) | ((uint32_t)__bfloat16_as_ushort(h3) << 16);
    pl[0] = (uint32_t)__bfloat16_as_ushort(l0) | ((uint32_t)__bfloat16_as_ushort(l1) << 16);
    pl[1] = (uint32_t)__bfloat16_as_ushort(l2) | ((uint32_t)__bfloat16_as_ushort(l3) << 16);
}

// h [N_USERS x 128] f32  ->  Bt_hi/Bt_lo [128 x KPAD] bf16 (transposed split)
__global__ void conv_Bt(const float* __restrict__ h,
                        __nv_bfloat16* __restrict__ Bhi, __nv_bfloat16* __restrict__ Blo)
{
    __shared__ float t[32][33];
    int k0 = blockIdx.x * 32;
    int n0 = blockIdx.y * 32;
    int tx = threadIdx.x, ty = threadIdx.y;   // 32 x 8
#pragma unroll
    for (int r = 0; r < 4; r++) {
        int k = k0 + ty + r * 8;
        if (k < N_USERS) t[ty + r * 8][tx] = h[(size_t)k * NCOL + n0 + tx];
    }
    __syncthreads();
#pragma unroll
    for (int r = 0; r < 4; r++) {
        int n = n0 + ty + r * 8;
        int k = k0 + tx;
        if (k < N_USERS) {
            float v = t[tx][ty + r * 8];
            __nv_bfloat16 hi = __float2bfloat16(v);
            __nv_bfloat16 lo = __float2bfloat16(v - __bfloat162float(hi));
            Bhi[(size_t)n * KPAD + k] = hi;
            Blo[(size_t)n * KPAD + k] = lo;
        }
    }
}

// ---------------- mma.sync bf16 GEMM: C[MPAD,128] += 3-term split ------------
// R4-proven body; grid = 79 m-tiles x 4 k-splits = 316 CTAs (balanced waves).
__global__ __launch_bounds__(256)
void gemm_social(const __nv_bfloat16* __restrict__ Ahi, const __nv_bfloat16* __restrict__ Alo,
                 const __nv_bfloat16* __restrict__ Bhi, const __nv_bfloat16* __restrict__ Blo,
                 float* __restrict__ C)
{
    __shared__ __align__(16) char smem[2 * STAGE];
    const uint32_t sbase = smem_u32(smem);
    const int tid = threadIdx.x;
    const int wid = tid >> 5, lane = tid & 31;
    const int wm = (wid >> 2) * 64;        // warp M offset in tile
    const int wn = (wid & 3) * 32;         // warp N offset
    const int m0 = (blockIdx.x >> 2) * 128;
    const size_t kbase = (size_t)(blockIdx.x & 3) * KSPLIT;

    float d[4][4][4];
#pragma unroll
    for (int a = 0; a < 4; a++)
#pragma unroll
        for (int b = 0; b < 4; b++)
#pragma unroll
            for (int c = 0; c < 4; c++) d[a][b][c] = 0.f;

    const int lr  = tid >> 2;          // 0..63 base row (x2)
    const int lc  = tid & 3;           // 16B chunk within 64B row segment

    const int arow = (lane & 7) + ((lane >> 3) & 1) * 8;
    const int acol = (lane >> 4) * 16;
    const int brow = ((lane >> 4) * 8) + (lane & 7);
    const int bcol = ((lane >> 3) & 1) * 16;

#define PREFETCH(IT)                                                              \
    {                                                                             \
        int ph = (IT) / KCH2;                                                     \
        int kc = (IT) - ph * KCH2;                                                \
        const __nv_bfloat16* Ap = (ph == 2) ? Alo : Ahi;                          \
        const __nv_bfloat16* Bp = (ph == 1) ? Blo : Bhi;                          \
        size_t koff = kbase + (size_t)kc * 32;                                    \
        uint32_t dA = sbase + ((IT) & 1) * STAGE;                                 \
        uint32_t dB = dA + ASZ;                                                   \
        _Pragma("unroll")                                                         \
        for (int j = 0; j < 2; j++) {                                             \
            int r = lr + j * 64;                                                  \
            CPASYNC(dA + r * ROWB + lc * 16,                                      \
                    Ap + (size_t)(m0 + r) * KPAD + koff + lc * 8);                \
            CPASYNC(dB + r * ROWB + lc * 16,                                      \
                    Bp + (size_t)r * KPAD + koff + lc * 8);                       \
        }                                                                         \
    }

    PREFETCH(0)
    CPCOMMIT();

#pragma unroll 1
    for (int it = 0; it < NITER; it++) {
        if (it + 1 < NITER) {
            PREFETCH(it + 1)
            CPCOMMIT();
            CPWAIT(1);
        } else {
            CPWAIT(0);
        }
        __syncthreads();

        uint32_t sA = sbase + (it & 1) * STAGE;
        uint32_t sB = sA + ASZ;

#pragma unroll
        for (int kk = 0; kk < 2; kk++) {           // two k16 steps in BK=32
            uint32_t a[4][4], b[4][2];
#pragma unroll
            for (int mt = 0; mt < 4; mt++) {
                uint32_t addr = sA + (wm + mt * 16 + arow) * ROWB + kk * 32 + acol;
                LDSM4(a[mt][0], a[mt][1], a[mt][2], a[mt][3], addr);
            }
#pragma unroll
            for (int bt = 0; bt < 2; bt++) {
                uint32_t addr = sB + (wn + bt * 16 + brow) * ROWB + kk * 32 + bcol;
                LDSM4(b[bt * 2][0], b[bt * 2][1], b[bt * 2 + 1][0], b[bt * 2 + 1][1], addr);
            }
#pragma unroll
            for (int mt = 0; mt < 4; mt++)
#pragma unroll
                for (int nt = 0; nt < 4; nt++)
                    MMA_BF16(d[mt][nt], a[mt], b[nt]);
        }
        __syncthreads();
    }

    // epilogue: red.global.add.v2 into zeroed C (split-K accumulate)
    const int rbase = m0 + wm + (lane >> 2);
    const int cbase = wn + 2 * (lane & 3);
#pragma unroll
    for (int mt = 0; mt < 4; mt++) {
        int r0 = rbase + mt * 16;
#pragma unroll
        for (int nt = 0; nt < 4; nt++) {
            int c = cbase + nt * 8;
            red_add_v2(C + (size_t)r0 * NCOL + c,       d[mt][nt][0], d[mt][nt][1]);
            red_add_v2(C + (size_t)(r0 + 8) * NCOL + c, d[mt][nt][2], d[mt][nt][3]);
        }
    }
}

// ---------------- init kernels ----------------------------------------------
__global__ void init_social(const float* __restrict__ ue, const float* __restrict__ u1,
                            float* __restrict__ H, float* __restrict__ acc) {
    int idx = blockIdx.x * blockDim.x + threadIdx.x;
    if (idx >= N_USERS * HID) return;
    int u = idx >> 6, c = idx & 63;
    float a = ue[idx], b = u1[idx];
    H[u * NCOL + c] = a;        H[u * NCOL + 64 + c] = b;
    acc[u * NCOL + c] = a;      acc[u * NCOL + 64 + c] = b;
}

__global__ void init_ui(const float* __restrict__ ue, const float* __restrict__ ie,
                        const float* __restrict__ u2, const float* __restrict__ i2,
                        float* __restrict__ H, float* __restrict__ acc) {
    int idx = blockIdx.x * blockDim.x + threadIdx.x;
    if (idx >= N_TOT * HID) return;
    int n = idx >> 6, c = idx & 63;
    float a, b;
    if (n < N_USERS) { a = ue[n * 64 + c];              b = u2[n * 64 + c]; }
    else             { int m = n - N_USERS; a = ie[(size_t)m * 64 + c]; b = i2[(size_t)m * 64 + c]; }
    H[n * NCOL + c] = a;        H[n * NCOL + 64 + c] = b;
    acc[n * NCOL + c] = a;      acc[n * NCOL + 64 + c] = b;
}

// ---------------- sparse SpMM: one warp per edge ----------------------------
__global__ void spmm_kernel(const int* __restrict__ rows, const int* __restrict__ cols,
                            const float* __restrict__ vals,
                            const float* __restrict__ H, float* __restrict__ Hout, int nnz)
{
    int warp = (blockIdx.x * blockDim.x + threadIdx.x) >> 5;
    int lane = threadIdx.x & 31;
    if (warp >= nnz) return;
    int r = rows[warp];
    int c = cols[warp];
    float v = vals[warp];
    const float4 h = *(const float4*)(H + (size_t)c * NCOL + lane * 4);
    red_add_v4(Hout + (size_t)r * NCOL + lane * 4, h.x * v, h.y * v, h.z * v, h.w * v);
}

__global__ void add_acc(float4* __restrict__ acc, const float4* __restrict__ h, int n4) {
    int i = blockIdx.x * blockDim.x + threadIdx.x;
    if (i < n4) {
        float4 a = acc[i], b = h[i];
        a.x += b.x; a.y += b.y; a.z += b.z; a.w += b.w;
        acc[i] = a;
    }
}

// ---------------- finalize ---------------------------------------------------
__global__ void finalize(const float* __restrict__ accS, const float* __restrict__ accA,
                         const float* __restrict__ item1,
                         const int* __restrict__ users, const int* __restrict__ pos,
                         const int* __restrict__ neg, float* __restrict__ out)
{
    const int TOTROWS = 9 * BATCH + 2 * N_USERS;
    int gid = blockIdx.x * blockDim.x + threadIdx.x;
    if (gid >= TOTROWS * 64) return;
    int row = gid >> 6, c = gid & 63;
    float v;
    if (row < BATCH) {
        int u = users[row];
        v = (accS[u * NCOL + c] + accA[u * NCOL + c]) * 0.125f;
    } else if (row < 2 * BATCH) {
        int i = pos[row - BATCH];
        v = accA[(size_t)(N_USERS + i) * NCOL + c] * 0.25f;
    } else if (row < 3 * BATCH) {
        int i = neg[row - 2 * BATCH];
        v = accA[(size_t)(N_USERS + i) * NCOL + c] * 0.25f;
    } else if (row < 3 * BATCH + N_USERS) {
        int u = row - 3 * BATCH;
        v = accS[u * NCOL + c] * 0.25f;
    } else if (row < 3 * BATCH + 2 * N_USERS) {
        int u = row - 3 * BATCH - N_USERS;
        v = accA[u * NCOL + c] * 0.25f;
    } else if (row < 4 * BATCH + 2 * N_USERS) {
        int u = users[row - 3 * BATCH - 2 * N_USERS];
        v = accS[u * NCOL + 64 + c] * 0.25f;
    } else if (row < 5 * BATCH + 2 * N_USERS) {
        int i = pos[row - 4 * BATCH - 2 * N_USERS];
        v = item1[(size_t)i * 64 + c];
    } else if (row < 6 * BATCH + 2 * N_USERS) {
        int i = neg[row - 5 * BATCH - 2 * N_USERS];
        v = item1[(size_t)i * 64 + c];
    } else if (row < 7 * BATCH + 2 * N_USERS) {
        int u = users[row - 6 * BATCH - 2 * N_USERS];
        v = accA[u * NCOL + 64 + c] * 0.25f;
    } else if (row < 8 * BATCH + 2 * N_USERS) {
        int i = pos[row - 7 * BATCH - 2 * N_USERS];
        v = accA[(size_t)(N_USERS + i) * NCOL + 64 + c] * 0.25f;
    } else {
        int i = neg[row - 8 * BATCH - 2 * N_USERS];
        v = accA[(size_t)(N_USERS + i) * NCOL + 64 + c] * 0.25f;
    }
    out[gid] = v;
}

// ---------------- launch (single stream, R4 structure) -----------------------
extern "C" void kernel_launch(void* const* d_in, const int* in_sizes, int n_in,
                              void* d_out, int out_size)
{
    const int*   users = (const int*)d_in[0];
    const int*   pos   = (const int*)d_in[1];
    const int*   neg   = (const int*)d_in[2];
    const float* ue    = (const float*)d_in[3];
    const float* ie    = (const float*)d_in[4];
    const float* u1    = (const float*)d_in[5];
    const float* i1    = (const float*)d_in[6];
    const float* u2    = (const float*)d_in[7];
    const float* i2    = (const float*)d_in[8];
    const float* S     = (const float*)d_in[9];
    const int*   arows = (const int*)d_in[10];
    const int*   acols = (const int*)d_in[11];
    const float* avals = (const float*)d_in[12];
    float* out = (float*)d_out;

    __nv_bfloat16 *Ahi, *Alo, *Bhi, *Blo;
    float *C1, *C2, *Hs, *aS, *Ha, *Ha2, *aA;
    cudaGetSymbolAddress((void**)&Ahi, g_Ahi);
    cudaGetSymbolAddress((void**)&Alo, g_Alo);
    cudaGetSymbolAddress((void**)&Bhi, g_Bhi);
    cudaGetSymbolAddress((void**)&Blo, g_Blo);
    cudaGetSymbolAddress((void**)&C1,  g_C1);
    cudaGetSymbolAddress((void**)&C2,  g_C2);
    cudaGetSymbolAddress((void**)&Hs,  g_Hs);
    cudaGetSymbolAddress((void**)&aS,  g_accS);
    cudaGetSymbolAddress((void**)&Ha,  g_Ha);
    cudaGetSymbolAddress((void**)&Ha2, g_Ha2);
    cudaGetSymbolAddress((void**)&aA,  g_accA);

    init_social<<<(N_USERS * HID + 255) / 256, 256>>>(ue, u1, Hs, aS);
    init_ui<<<(N_TOT * HID + 255) / 256, 256>>>(ue, ie, u2, i2, Ha, aA);

    // one-time split of S into bf16 hi/lo (padded, padding stays zero)
    conv_S<<<(N_USERS * 2500 + 255) / 256, 256>>>((const float4*)S, Ahi, Alo);

    // social: 3 hops of mma.sync split-bf16 GEMM (split-K=4, balanced grid)
    {
        float* cur = Hs;
        for (int h = 0; h < HOPS; h++) {
            conv_Bt<<<dim3((N_USERS + 31) / 32, 4), dim3(32, 8)>>>(cur, Bhi, Blo);
            float* nxt = (h & 1) ? C2 : C1;
            cudaMemsetAsync(nxt, 0, (size_t)MPAD * NCOL * sizeof(float));
            gemm_social<<<79 * KSPLITN, 256>>>(Ahi, Alo, Bhi, Blo, nxt);
            add_acc<<<(N_USERS * NCOL / 4 + 255) / 256, 256>>>(
                (float4*)aS, (const float4*)nxt, N_USERS * NCOL / 4);
            cur = nxt;
        }
    }

    // user-item: 3 hops of sparse SpMM over 2M edges, 128 cols
    {
        float* cur = Ha; float* nxt = Ha2;
        for (int h = 0; h < HOPS; h++) {
            cudaMemsetAsync(nxt, 0, (size_t)N_TOT * NCOL * sizeof(float));
            spmm_kernel<<<(NNZ_ + 7) / 8, 256>>>(arows, acols, avals, cur, nxt, NNZ_);
            add_acc<<<(N_TOT * NCOL / 4 + 255) / 256, 256>>>(
                (float4*)aA, (const float4*)nxt, N_TOT * NCOL / 4);
            float* t = cur; cur = nxt; nxt = t;
        }
    }

    const int totrows = 9 * BATCH + 2 * N_USERS;
    finalize<<<(totrows * 64 + 255) / 256, 256>>>(aS, aA, i1, users, pos, neg, out);
}

// round 10
// speedup vs baseline: 2.0241x; 1.1242x over previous
#include <cuda_runtime.h>
#include <cuda_bf16.h>
#include <cstdint>

#define N_USERS 10000
#define N_ITEMS 40000
#define N_TOT   50000
#define HID     64
#define NCOL    128
#define NNZ_    2000000
#define BATCH   8192
#define HOPS    3

// GEMM padding
#define MPAD    10112          // 79 * 128
#define KPAD    10112          // 316 * 32
#define KSPLITN 4
#define KSPLIT  2528           // KPAD / 4
#define KCH2    79             // KSPLIT / 32  == iterations per CTA (single sweep)

// smem stage: 4 tiles (Ahi, Alo, Bhi, Blo), each 128 rows x 80B
#define ROWB    80
#define TILE    (128 * ROWB)       // 10240
#define STAGE4  (4 * TILE)         // 40960
#define GEMM_SMEM (2 * STAGE4)     // 81920, double-buffered

// ---------------- scratch (__device__ globals; zero-init => padding stays 0) --
__device__ __nv_bfloat16 g_Ahi[(size_t)MPAD * KPAD];
__device__ __nv_bfloat16 g_Alo[(size_t)MPAD * KPAD];
__device__ __nv_bfloat16 g_Bhi[(size_t)128 * KPAD];
__device__ __nv_bfloat16 g_Blo[(size_t)128 * KPAD];
__device__ float g_C1[(size_t)MPAD * NCOL];
__device__ float g_C2[(size_t)MPAD * NCOL];
__device__ float g_Hs [N_USERS * NCOL];
__device__ float g_accS[N_USERS * NCOL];
__device__ float g_Ha [N_TOT * NCOL];
__device__ float g_Ha2[N_TOT * NCOL];
__device__ float g_accA[N_TOT * NCOL];

// ---------------- PTX helpers ------------------------------------------------
__device__ __forceinline__ void red_add_v4(float* addr, float x, float y, float z, float w) {
    asm volatile("red.global.add.v4.f32 [%0], {%1, %2, %3, %4};"
                 :: "l"(addr), "f"(x), "f"(y), "f"(z), "f"(w) : "memory");
}
__device__ __forceinline__ void red_add_v2(float* addr, float x, float y) {
    asm volatile("red.global.add.v2.f32 [%0], {%1, %2};"
                 :: "l"(addr), "f"(x), "f"(y) : "memory");
}

__device__ __forceinline__ uint32_t smem_u32(const void* p) {
    uint32_t a;
    asm("{ .reg .u64 t; cvta.to.shared.u64 t, %1; cvt.u32.u64 %0, t; }" : "=r"(a) : "l"(p));
    return a;
}

#define CPASYNC(dst, src) \
    asm volatile("cp.async.cg.shared.global [%0], [%1], 16;" :: "r"(dst), "l"(src) : "memory")
#define CPCOMMIT() asm volatile("cp.async.commit_group;" ::: "memory")
#define CPWAIT(n)  asm volatile("cp.async.wait_group %0;" :: "n"(n) : "memory")

#define LDSM4(r0, r1, r2, r3, addr)                                              \
    asm volatile("ldmatrix.sync.aligned.m8n8.x4.shared.b16 {%0,%1,%2,%3}, [%4];" \
                 : "=r"(r0), "=r"(r1), "=r"(r2), "=r"(r3) : "r"(addr))

#define MMA_BF16(d, a, b)                                                        \
    asm volatile("mma.sync.aligned.m16n8k16.row.col.f32.bf16.bf16.f32 "          \
                 "{%0,%1,%2,%3}, {%4,%5,%6,%7}, {%8,%9}, {%0,%1,%2,%3};"         \
                 : "+f"((d)[0]), "+f"((d)[1]), "+f"((d)[2]), "+f"((d)[3])        \
                 : "r"((a)[0]), "r"((a)[1]), "r"((a)[2]), "r"((a)[3]),           \
                   "r"((b)[0]), "r"((b)[1]))

// ---------------- split conversions ------------------------------------------
__global__ void conv_S(const float4* __restrict__ S4,
                       __nv_bfloat16* __restrict__ Ahi, __nv_bfloat16* __restrict__ Alo)
{
    int i = blockIdx.x * blockDim.x + threadIdx.x;
    if (i >= N_USERS * 2500) return;
    int m = i / 2500, k4 = i - m * 2500;
    float4 v = S4[i];
    size_t o = (size_t)m * KPAD + (size_t)k4 * 4;
    __nv_bfloat16 h0 = __float2bfloat16(v.x), h1 = __float2bfloat16(v.y);
    __nv_bfloat16 h2 = __float2bfloat16(v.z), h3 = __float2bfloat16(v.w);
    __nv_bfloat16 l0 = __float2bfloat16(v.x - __bfloat162float(h0));
    __nv_bfloat16 l1 = __float2bfloat16(v.y - __bfloat162float(h1));
    __nv_bfloat16 l2 = __float2bfloat16(v.z - __bfloat162float(h2));
    __nv_bfloat16 l3 = __float2bfloat16(v.w - __bfloat162float(h3));
    uint32_t* ph = reinterpret_cast<uint32_t*>(Ahi + o);
    uint32_t* pl = reinterpret_cast<uint32_t*>(Alo + o);
    ph[0] = (uint32_t)__bfloat16_as_ushort(h0) | ((uint32_t)__bfloat16_as_ushort(h1) << 16);
    ph[1] = (uint32_t)__bfloat16_as_ushort(h2) | ((uint32_t)__bfloat16_as_ushort(h3) << 16);
    pl[0] = (uint32_t)__bfloat16_as_ushort(l0) | ((uint32_t)__bfloat16_as_ushort(l1) << 16);
    pl[1] = (uint32_t)__bfloat16_as_ushort(l2) | ((uint32_t)__bfloat16_as_ushort(l3) << 16);
}

// h [N_USERS x 128] f32  ->  Bt_hi/Bt_lo [128 x KPAD] bf16 (transposed split)
__global__ void conv_Bt(const float* __restrict__ h,
                        __nv_bfloat16* __restrict__ Bhi, __nv_bfloat16* __restrict__ Blo)
{
    __shared__ float t[32][33];
    int k0 = blockIdx.x * 32;
    int n0 = blockIdx.y * 32;
    int tx = threadIdx.x, ty = threadIdx.y;   // 32 x 8
#pragma unroll
    for (int r = 0; r < 4; r++) {
        int k = k0 + ty + r * 8;
        if (k < N_USERS) t[ty + r * 8][tx] = h[(size_t)k * NCOL + n0 + tx];
    }
    __syncthreads();
#pragma unroll
    for (int r = 0; r < 4; r++) {
        int n = n0 + ty + r * 8;
        int k = k0 + tx;
        if (k < N_USERS) {
            float v = t[tx][ty + r * 8];
            __nv_bfloat16 hi = __float2bfloat16(v);
            __nv_bfloat16 lo = __float2bfloat16(v - __bfloat162float(hi));
            Bhi[(size_t)n * KPAD + k] = hi;
            Blo[(size_t)n * KPAD + k] = lo;
        }
    }
}

// ---------------- mma.sync bf16 GEMM: C[MPAD,128] += 3-term split ------------
// Single K-sweep: each chunk holds Ahi/Alo/Bhi/Blo; all 3 term-products per
// chunk accumulate into the same fp32 d. Grid = 79 m-tiles x 4 k-splits.
__global__ __launch_bounds__(256, 2)
void gemm_social(const __nv_bfloat16* __restrict__ Ahi, const __nv_bfloat16* __restrict__ Alo,
                 const __nv_bfloat16* __restrict__ Bhi, const __nv_bfloat16* __restrict__ Blo,
                 float* __restrict__ C)
{
    extern __shared__ __align__(16) char smem[];
    const uint32_t sbase = smem_u32(smem);
    const int tid = threadIdx.x;
    const int wid = tid >> 5, lane = tid & 31;
    const int wm = (wid >> 2) * 64;        // warp M offset in tile
    const int wn = (wid & 3) * 32;         // warp N offset
    const int m0 = (blockIdx.x >> 2) * 128;
    const size_t kbase = (size_t)(blockIdx.x & 3) * KSPLIT;

    float d[4][4][4];
#pragma unroll
    for (int a = 0; a < 4; a++)
#pragma unroll
        for (int b = 0; b < 4; b++)
#pragma unroll
            for (int c = 0; c < 4; c++) d[a][b][c] = 0.f;

    const int lr  = tid >> 2;          // 0..63 base row (x2)
    const int lc  = tid & 3;           // 16B chunk within 64B row segment

    const int arow = (lane & 7) + ((lane >> 3) & 1) * 8;
    const int acol = (lane >> 4) * 16;
    const int brow = ((lane >> 4) * 8) + (lane & 7);
    const int bcol = ((lane >> 3) & 1) * 16;

    const __nv_bfloat16* gAhi = Ahi + (size_t)m0 * KPAD + kbase;
    const __nv_bfloat16* gAlo = Alo + (size_t)m0 * KPAD + kbase;
    const __nv_bfloat16* gBhi = Bhi + kbase;
    const __nv_bfloat16* gBlo = Blo + kbase;

#define PREFETCH(IT)                                                              \
    {                                                                             \
        size_t koff = (size_t)(IT) * 32;                                          \
        uint32_t st = sbase + ((IT) & 1) * STAGE4;                                \
        _Pragma("unroll")                                                         \
        for (int j = 0; j < 2; j++) {                                             \
            int r = lr + j * 64;                                                  \
            uint32_t so = r * ROWB + lc * 16;                                     \
            size_t ao = (size_t)r * KPAD + koff + lc * 8;                         \
            CPASYNC(st + so,            gAhi + ao);                               \
            CPASYNC(st + TILE + so,     gAlo + ao);                               \
            CPASYNC(st + 2 * TILE + so, gBhi + ao);                               \
            CPASYNC(st + 3 * TILE + so, gBlo + ao);                               \
        }                                                                         \
    }

    PREFETCH(0)
    CPCOMMIT();

#pragma unroll 1
    for (int it = 0; it < KCH2; it++) {
        if (it + 1 < KCH2) {
            PREFETCH(it + 1)
            CPCOMMIT();
            CPWAIT(1);
        } else {
            CPWAIT(0);
        }
        __syncthreads();

        uint32_t st = sbase + (it & 1) * STAGE4;

#pragma unroll
        for (int kk = 0; kk < 2; kk++) {           // two k16 steps in BK=32
            uint32_t a[4][4], bh[4][2], bl[4][2];
            // B tiles (hi + lo)
#pragma unroll
            for (int bt = 0; bt < 2; bt++) {
                uint32_t boff = (wn + bt * 16 + brow) * ROWB + kk * 32 + bcol;
                LDSM4(bh[bt * 2][0], bh[bt * 2][1], bh[bt * 2 + 1][0], bh[bt * 2 + 1][1],
                      st + 2 * TILE + boff);
                LDSM4(bl[bt * 2][0], bl[bt * 2][1], bl[bt * 2 + 1][0], bl[bt * 2 + 1][1],
                      st + 3 * TILE + boff);
            }
            // Ahi: feeds both Bhi and Blo products
#pragma unroll
            for (int mt = 0; mt < 4; mt++) {
                uint32_t aoff = (wm + mt * 16 + arow) * ROWB + kk * 32 + acol;
                LDSM4(a[mt][0], a[mt][1], a[mt][2], a[mt][3], st + aoff);
            }
#pragma unroll
            for (int mt = 0; mt < 4; mt++)
#pragma unroll
                for (int nt = 0; nt < 4; nt++)
                    MMA_BF16(d[mt][nt], a[mt], bh[nt]);
#pragma unroll
            for (int mt = 0; mt < 4; mt++)
#pragma unroll
                for (int nt = 0; nt < 4; nt++)
                    MMA_BF16(d[mt][nt], a[mt], bl[nt]);
            // Alo (overwrite a regs): feeds Bhi product
#pragma unroll
            for (int mt = 0; mt < 4; mt++) {
                uint32_t aoff = (wm + mt * 16 + arow) * ROWB + kk * 32 + acol;
                LDSM4(a[mt][0], a[mt][1], a[mt][2], a[mt][3], st + TILE + aoff);
            }
#pragma unroll
            for (int mt = 0; mt < 4; mt++)
#pragma unroll
                for (int nt = 0; nt < 4; nt++)
                    MMA_BF16(d[mt][nt], a[mt], bh[nt]);
        }
        __syncthreads();
    }

    // epilogue: red.global.add.v2 into zeroed C (split-K accumulate)
    const int rbase = m0 + wm + (lane >> 2);
    const int cbase = wn + 2 * (lane & 3);
#pragma unroll
    for (int mt = 0; mt < 4; mt++) {
        int r0 = rbase + mt * 16;
#pragma unroll
        for (int nt = 0; nt < 4; nt++) {
            int c = cbase + nt * 8;
            red_add_v2(C + (size_t)r0 * NCOL + c,       d[mt][nt][0], d[mt][nt][1]);
            red_add_v2(C + (size_t)(r0 + 8) * NCOL + c, d[mt][nt][2], d[mt][nt][3]);
        }
    }
}

// ---------------- init kernels ----------------------------------------------
__global__ void init_social(const float* __restrict__ ue, const float* __restrict__ u1,
                            float* __restrict__ H, float* __restrict__ acc) {
    int idx = blockIdx.x * blockDim.x + threadIdx.x;
    if (idx >= N_USERS * HID) return;
    int u = idx >> 6, c = idx & 63;
    float a = ue[idx], b = u1[idx];
    H[u * NCOL + c] = a;        H[u * NCOL + 64 + c] = b;
    acc[u * NCOL + c] = a;      acc[u * NCOL + 64 + c] = b;
}

__global__ void init_ui(const float* __restrict__ ue, const float* __restrict__ ie,
                        const float* __restrict__ u2, const float* __restrict__ i2,
                        float* __restrict__ H, float* __restrict__ acc) {
    int idx = blockIdx.x * blockDim.x + threadIdx.x;
    if (idx >= N_TOT * HID) return;
    int n = idx >> 6, c = idx & 63;
    float a, b;
    if (n < N_USERS) { a = ue[n * 64 + c];              b = u2[n * 64 + c]; }
    else             { int m = n - N_USERS; a = ie[(size_t)m * 64 + c]; b = i2[(size_t)m * 64 + c]; }
    H[n * NCOL + c] = a;        H[n * NCOL + 64 + c] = b;
    acc[n * NCOL + c] = a;      acc[n * NCOL + 64 + c] = b;
}

// ---------------- sparse SpMM: one warp per edge ----------------------------
__global__ void spmm_kernel(const int* __restrict__ rows, const int* __restrict__ cols,
                            const float* __restrict__ vals,
                            const float* __restrict__ H, float* __restrict__ Hout, int nnz)
{
    int warp = (blockIdx.x * blockDim.x + threadIdx.x) >> 5;
    int lane = threadIdx.x & 31;
    if (warp >= nnz) return;
    int r = rows[warp];
    int c = cols[warp];
    float v = vals[warp];
    const float4 h = *(const float4*)(H + (size_t)c * NCOL + lane * 4);
    red_add_v4(Hout + (size_t)r * NCOL + lane * 4, h.x * v, h.y * v, h.z * v, h.w * v);
}

__global__ void add_acc(float4* __restrict__ acc, const float4* __restrict__ h, int n4) {
    int i = blockIdx.x * blockDim.x + threadIdx.x;
    if (i < n4) {
        float4 a = acc[i], b = h[i];
        a.x += b.x; a.y += b.y; a.z += b.z; a.w += b.w;
        acc[i] = a;
    }
}

// ---------------- finalize ---------------------------------------------------
__global__ void finalize(const float* __restrict__ accS, const float* __restrict__ accA,
                         const float* __restrict__ item1,
                         const int* __restrict__ users, const int* __restrict__ pos,
                         const int* __restrict__ neg, float* __restrict__ out)
{
    const int TOTROWS = 9 * BATCH + 2 * N_USERS;
    int gid = blockIdx.x * blockDim.x + threadIdx.x;
    if (gid >= TOTROWS * 64) return;
    int row = gid >> 6, c = gid & 63;
    float v;
    if (row < BATCH) {
        int u = users[row];
        v = (accS[u * NCOL + c] + accA[u * NCOL + c]) * 0.125f;
    } else if (row < 2 * BATCH) {
        int i = pos[row - BATCH];
        v = accA[(size_t)(N_USERS + i) * NCOL + c] * 0.25f;
    } else if (row < 3 * BATCH) {
        int i = neg[row - 2 * BATCH];
        v = accA[(size_t)(N_USERS + i) * NCOL + c] * 0.25f;
    } else if (row < 3 * BATCH + N_USERS) {
        int u = row - 3 * BATCH;
        v = accS[u * NCOL + c] * 0.25f;
    } else if (row < 3 * BATCH + 2 * N_USERS) {
        int u = row - 3 * BATCH - N_USERS;
        v = accA[u * NCOL + c] * 0.25f;
    } else if (row < 4 * BATCH + 2 * N_USERS) {
        int u = users[row - 3 * BATCH - 2 * N_USERS];
        v = accS[u * NCOL + 64 + c] * 0.25f;
    } else if (row < 5 * BATCH + 2 * N_USERS) {
        int i = pos[row - 4 * BATCH - 2 * N_USERS];
        v = item1[(size_t)i * 64 + c];
    } else if (row < 6 * BATCH + 2 * N_USERS) {
        int i = neg[row - 5 * BATCH - 2 * N_USERS];
        v = item1[(size_t)i * 64 + c];
    } else if (row < 7 * BATCH + 2 * N_USERS) {
        int u = users[row - 6 * BATCH - 2 * N_USERS];
        v = accA[u * NCOL + 64 + c] * 0.25f;
    } else if (row < 8 * BATCH + 2 * N_USERS) {
        int i = pos[row - 7 * BATCH - 2 * N_USERS];
        v = accA[(size_t)(N_USERS + i) * NCOL + 64 + c] * 0.25f;
    } else {
        int i = neg[row - 8 * BATCH - 2 * N_USERS];
        v = accA[(size_t)(N_USERS + i) * NCOL + 64 + c] * 0.25f;
    }
    out[gid] = v;
}

// ---------------- launch (single stream) -------------------------------------
extern "C" void kernel_launch(void* const* d_in, const int* in_sizes, int n_in,
                              void* d_out, int out_size)
{
    const int*   users = (const int*)d_in[0];
    const int*   pos   = (const int*)d_in[1];
    const int*   neg   = (const int*)d_in[2];
    const float* ue    = (const float*)d_in[3];
    const float* ie    = (const float*)d_in[4];
    const float* u1    = (const float*)d_in[5];
    const float* i1    = (const float*)d_in[6];
    const float* u2    = (const float*)d_in[7];
    const float* i2    = (const float*)d_in[8];
    const float* S     = (const float*)d_in[9];
    const int*   arows = (const int*)d_in[10];
    const int*   acols = (const int*)d_in[11];
    const float* avals = (const float*)d_in[12];
    float* out = (float*)d_out;

    __nv_bfloat16 *Ahi, *Alo, *Bhi, *Blo;
    float *C1, *C2, *Hs, *aS, *Ha, *Ha2, *aA;
    cudaGetSymbolAddress((void**)&Ahi, g_Ahi);
    cudaGetSymbolAddress((void**)&Alo, g_Alo);
    cudaGetSymbolAddress((void**)&Bhi, g_Bhi);
    cudaGetSymbolAddress((void**)&Blo, g_Blo);
    cudaGetSymbolAddress((void**)&C1,  g_C1);
    cudaGetSymbolAddress((void**)&C2,  g_C2);
    cudaGetSymbolAddress((void**)&Hs,  g_Hs);
    cudaGetSymbolAddress((void**)&aS,  g_accS);
    cudaGetSymbolAddress((void**)&Ha,  g_Ha);
    cudaGetSymbolAddress((void**)&Ha2, g_Ha2);
    cudaGetSymbolAddress((void**)&aA,  g_accA);

    cudaFuncSetAttribute(gemm_social, cudaFuncAttributeMaxDynamicSharedMemorySize, GEMM_SMEM);

    init_social<<<(N_USERS * HID + 255) / 256, 256>>>(ue, u1, Hs, aS);
    init_ui<<<(N_TOT * HID + 255) / 256, 256>>>(ue, ie, u2, i2, Ha, aA);

    // one-time split of S into bf16 hi/lo (padded, padding stays zero)
    conv_S<<<(N_USERS * 2500 + 255) / 256, 256>>>((const float4*)S, Ahi, Alo);

    // social: 3 hops of mma.sync split-bf16 GEMM (single K-sweep, 3 terms/chunk)
    {
        float* cur = Hs;
        for (int h = 0; h < HOPS; h++) {
            conv_Bt<<<dim3((N_USERS + 31) / 32, 4), dim3(32, 8)>>>(cur, Bhi, Blo);
            float* nxt = (h & 1) ? C2 : C1;
            cudaMemsetAsync(nxt, 0, (size_t)MPAD * NCOL * sizeof(float));
            gemm_social<<<79 * KSPLITN, 256, GEMM_SMEM>>>(Ahi, Alo, Bhi, Blo, nxt);
            add_acc<<<(N_USERS * NCOL / 4 + 255) / 256, 256>>>(
                (float4*)aS, (const float4*)nxt, N_USERS * NCOL / 4);
            cur = nxt;
        }
    }

    // user-item: 3 hops of sparse SpMM over 2M edges, 128 cols
    {
        float* cur = Ha; float* nxt = Ha2;
        for (int h = 0; h < HOPS; h++) {
            cudaMemsetAsync(nxt, 0, (size_t)N_TOT * NCOL * sizeof(float));
            spmm_kernel<<<(NNZ_ + 7) / 8, 256>>>(arows, acols, avals, cur, nxt, NNZ_);
            add_acc<<<(N_TOT * NCOL / 4 + 255) / 256, 256>>>(
                (float4*)aA, (const float4*)nxt, N_TOT * NCOL / 4);
            float* t = cur; cur = nxt; nxt = t;
        }
    }

    const int totrows = 9 * BATCH + 2 * N_USERS;
    finalize<<<(totrows * 64 + 255) / 256, 256>>>(aS, aA, i1, users, pos, neg, out);
}